// round 2
// baseline (speedup 1.0000x reference)
#include <cuda_runtime.h>

#define BATCH 32
#define LQN   2048
#define LKN   50
#define DIN   1024
#define DVN   512

// Scratch (device globals; no allocations allowed)
__device__ float g_k[BATCH * LKN * DIN];                    // keys @ W_k      [B,50,1024]
__device__ float g_U[(size_t)BATCH * DIN * DVN];            // k^T @ W_o / 32  [B,1024,512]
__device__ float g_G[(size_t)BATCH * DIN * DVN];            // W_q @ U         [B,1024,512]
__device__ float g_T[(size_t)BATCH * DVN * DIN];            // attn @ values   [B,512,1024]

// ---------------------------------------------------------------------------
// Generic batched SGEMM: C[b] = alpha * A[b](MxK) @ B[b](KxN), row-major.
// N multiple of 128, K multiple of 16 (guaranteed by call sites). M guarded.
// TRANS_C: store C transposed (C[n*ldc + m]) — used to emit attn in [v, q] layout.
// ---------------------------------------------------------------------------
template <bool TRANS_C>
__global__ __launch_bounds__(256)
void gemm128(const float* __restrict__ A, const float* __restrict__ Bm,
             float* __restrict__ C,
             int M, int N, int K,
             long long sA, long long sB, long long sC,
             int lda, int ldb, int ldc, float alpha)
{
    const int b = blockIdx.z;
    A  += (long long)b * sA;
    Bm += (long long)b * sB;
    C  += (long long)b * sC;

    const int bm = blockIdx.y * 128;
    const int bn = blockIdx.x * 128;

    __shared__ float As[16][128];
    __shared__ float Bs[16][128];

    const int tid = threadIdx.x;          // 0..255
    const int tx = tid & 15;              // N direction
    const int ty = tid >> 4;              // M direction

    float acc[8][8];
    #pragma unroll
    for (int i = 0; i < 8; i++)
        #pragma unroll
        for (int j = 0; j < 8; j++) acc[i][j] = 0.0f;

    for (int k0 = 0; k0 < K; k0 += 16) {
        // Load A tile 128x16 (transposed into As[k][m])
        #pragma unroll
        for (int l = 0; l < 2; l++) {
            int t   = tid + l * 256;      // 0..511
            int row = t >> 2;             // 0..127
            int col = (t & 3) << 2;       // 0,4,8,12
            float4 v = make_float4(0.f, 0.f, 0.f, 0.f);
            if (bm + row < M)
                v = *(const float4*)(A + (long long)(bm + row) * lda + k0 + col);
            As[col + 0][row] = v.x;
            As[col + 1][row] = v.y;
            As[col + 2][row] = v.z;
            As[col + 3][row] = v.w;
        }
        // Load B tile 16x128
        #pragma unroll
        for (int l = 0; l < 2; l++) {
            int t   = tid + l * 256;
            int row = t >> 5;             // 0..15
            int col = (t & 31) << 2;      // 0..124
            *(float4*)&Bs[row][col] =
                *(const float4*)(Bm + (long long)(k0 + row) * ldb + bn + col);
        }
        __syncthreads();

        #pragma unroll
        for (int kk = 0; kk < 16; kk++) {
            float a[8], bb[8];
            float4 a0 = *(const float4*)&As[kk][ty * 8];
            float4 a1 = *(const float4*)&As[kk][ty * 8 + 4];
            a[0]=a0.x; a[1]=a0.y; a[2]=a0.z; a[3]=a0.w;
            a[4]=a1.x; a[5]=a1.y; a[6]=a1.z; a[7]=a1.w;
            float4 b0 = *(const float4*)&Bs[kk][tx * 8];
            float4 b1 = *(const float4*)&Bs[kk][tx * 8 + 4];
            bb[0]=b0.x; bb[1]=b0.y; bb[2]=b0.z; bb[3]=b0.w;
            bb[4]=b1.x; bb[5]=b1.y; bb[6]=b1.z; bb[7]=b1.w;
            #pragma unroll
            for (int i = 0; i < 8; i++)
                #pragma unroll
                for (int j = 0; j < 8; j++)
                    acc[i][j] = fmaf(a[i], bb[j], acc[i][j]);
        }
        __syncthreads();
    }

    #pragma unroll
    for (int i = 0; i < 8; i++) {
        int m = bm + ty * 8 + i;
        if (m >= M) continue;
        #pragma unroll
        for (int j = 0; j < 8; j++) {
            int n = bn + tx * 8 + j;
            if (TRANS_C)
                C[(long long)n * ldc + m] = acc[i][j] * alpha;
            else
                C[(long long)m * ldc + n] = acc[i][j] * alpha;
        }
    }
}

// ---------------------------------------------------------------------------
// U[b,h,v] = (1/32) * sum_{kk<50} g_k[b,kk,h] * W_o[kk,v]
// ---------------------------------------------------------------------------
__global__ __launch_bounds__(256)
void u_kernel(const float* __restrict__ kmat, const float* __restrict__ Wo,
              float* __restrict__ U)
{
    const int b  = blockIdx.z;
    const int h0 = blockIdx.y * 32;
    const int v0 = blockIdx.x * 32;

    __shared__ float ks[LKN][32];
    __shared__ float wo[LKN][32];

    const int tid = threadIdx.x;
    for (int i = tid; i < LKN * 32; i += 256) {
        int kk = i >> 5, c = i & 31;
        ks[kk][c] = kmat[((long long)b * LKN + kk) * DIN + h0 + c];
        wo[kk][c] = Wo[kk * DVN + v0 + c];
    }
    __syncthreads();

    const int vv = tid & 31;
    const int h1 = (tid >> 5) * 4;      // 0,4,...,28
    float acc[4] = {0.f, 0.f, 0.f, 0.f};
    for (int kk = 0; kk < LKN; kk++) {
        float w = wo[kk][vv];
        #pragma unroll
        for (int i = 0; i < 4; i++) acc[i] = fmaf(ks[kk][h1 + i], w, acc[i]);
    }
    const float scale = 0.03125f;       // 1/sqrt(1024)
    #pragma unroll
    for (int i = 0; i < 4; i++)
        U[((long long)b * DIN + h0 + h1 + i) * DVN + v0 + vv] = acc[i] * scale;
}

// ---------------------------------------------------------------------------
// Masked softmax over q (len 2048) for each (b, v) row of attn [B, V, LQ].
// Positions q >= valid_len[b] are masked to -1e6 BEFORE softmax (in-place).
// ---------------------------------------------------------------------------
__global__ __launch_bounds__(256)
void softmax_mask(float* __restrict__ attn, const int* __restrict__ valid)
{
    const long long row = blockIdx.x;           // b*V + v
    const int b  = (int)(row / DVN);
    const int vl = valid[b];
    float* p = attn + row * (long long)LQN;

    const int tid = threadIdx.x;
    float v[8];
    float mx = -3.4e38f;
    #pragma unroll
    for (int i = 0; i < 8; i++) {
        int q = tid + i * 256;
        float x = p[q];
        x = (q < vl) ? x : -1000000.0f;
        v[i] = x;
        mx = fmaxf(mx, x);
    }

    __shared__ float red[256];
    red[tid] = mx;
    __syncthreads();
    for (int s = 128; s > 0; s >>= 1) {
        if (tid < s) red[tid] = fmaxf(red[tid], red[tid + s]);
        __syncthreads();
    }
    mx = red[0];
    __syncthreads();

    float sum = 0.0f;
    #pragma unroll
    for (int i = 0; i < 8; i++) { v[i] = expf(v[i] - mx); sum += v[i]; }
    red[tid] = sum;
    __syncthreads();
    for (int s = 128; s > 0; s >>= 1) {
        if (tid < s) red[tid] += red[tid + s];
        __syncthreads();
    }
    const float inv = 1.0f / red[0];

    #pragma unroll
    for (int i = 0; i < 8; i++) p[tid + i * 256] = v[i] * inv;
}

// ---------------------------------------------------------------------------
extern "C" void kernel_launch(void* const* d_in, const int* in_sizes, int n_in,
                              void* d_out, int out_size)
{
    const float* queries = (const float*)d_in[0];   // [32,2048,1024]
    const float* keys    = (const float*)d_in[1];   // [32,50,1024]
    const float* values  = (const float*)d_in[2];   // [32,2048,1024]
    const int*   valid   = (const int*)  d_in[3];   // [32]
    const float* Wq      = (const float*)d_in[4];   // [1024,1024]
    const float* Wk      = (const float*)d_in[5];   // [1024,1024]
    const float* Wv      = (const float*)d_in[6];   // [1024,1024]
    const float* Wo      = (const float*)d_in[7];   // [50,512]

    float* out  = (float*)d_out;                                    // [32,512,1024]
    float* attn = out + (size_t)BATCH * DVN * DIN;                  // [32,512,2048]

    float *pk, *pU, *pG, *pT;
    cudaGetSymbolAddress((void**)&pk, g_k);
    cudaGetSymbolAddress((void**)&pU, g_U);
    cudaGetSymbolAddress((void**)&pG, g_G);
    cudaGetSymbolAddress((void**)&pT, g_T);

    // K1: k = keys @ W_k            [B,50,1024]
    gemm128<false><<<dim3(DIN / 128, 1, BATCH), 256>>>(
        keys, Wk, pk, LKN, DIN, DIN,
        (long long)LKN * DIN, 0, (long long)LKN * DIN,
        DIN, DIN, DIN, 1.0f);

    // K2: U = k^T @ W_o / 32        [B,1024,512]
    u_kernel<<<dim3(DVN / 32, DIN / 32, BATCH), 256>>>(pk, Wo, pU);

    // K3: G = W_q @ U               [B,1024,512]
    gemm128<false><<<dim3(DVN / 128, DIN / 128, BATCH), 256>>>(
        Wq, pU, pG, DIN, DVN, DIN,
        0, (long long)DIN * DVN, (long long)DIN * DVN,
        DIN, DVN, DVN, 1.0f);

    // K4: S[b,v,q] = (queries @ G)^T  -> attn buffer (pre-softmax) [B,512,2048]
    gemm128<true><<<dim3(DVN / 128, LQN / 128, BATCH), 256>>>(
        queries, pG, attn, LQN, DVN, DIN,
        (long long)LQN * DIN, (long long)DIN * DVN, (long long)DVN * LQN,
        DIN, DVN, LQN, 1.0f);

    // K5: masked softmax over q, in place
    softmax_mask<<<BATCH * DVN, 256>>>(attn, valid);

    // K6: T = attn @ values          [B,512,1024]
    gemm128<false><<<dim3(DIN / 128, DVN / 128, BATCH), 256>>>(
        attn, values, pT, DVN, DIN, LQN,
        (long long)DVN * LQN, (long long)LQN * DIN, (long long)DVN * DIN,
        LQN, DIN, DIN, 1.0f);

    // K7: out = T @ W_v              [B,512,1024]
    gemm128<false><<<dim3(DIN / 128, DVN / 128, BATCH), 256>>>(
        pT, Wv, out, DVN, DIN, DIN,
        (long long)DVN * DIN, 0, (long long)DVN * DIN,
        DIN, DIN, DIN, 1.0f);
}

// round 4
// speedup vs baseline: 2.6812x; 2.6812x over previous
#include <cuda_runtime.h>
#include <cuda_bf16.h>
#include <cstdint>

#define BATCH 32
#define LQN   2048
#define LKN   50
#define DIN   1024
#define DVN   512

typedef __nv_bfloat16 bf16;

// ---------------------------------------------------------------------------
// Scratch (device globals; allocations are forbidden)
// ---------------------------------------------------------------------------
__device__ float g_k[BATCH * LKN * DIN];                         // keys @ W_k (fp32)
__device__ bf16  g_UtHi[(size_t)BATCH * DVN * DIN];              // (k^T W_o /32)^T  [B,512,1024]
__device__ bf16  g_UtLo[(size_t)BATCH * DVN * DIN];
__device__ bf16  g_WqHi[DIN * DIN];
__device__ bf16  g_WqLo[DIN * DIN];
__device__ bf16  g_GtHi[(size_t)BATCH * DVN * DIN];              // G^T [B,512,1024]
__device__ bf16  g_GtLo[(size_t)BATCH * DVN * DIN];
__device__ bf16  g_qHi[(size_t)BATCH * LQN * DIN];               // queries split [B,2048,1024]
__device__ bf16  g_qLo[(size_t)BATCH * LQN * DIN];
__device__ bf16  g_vTHi[(size_t)BATCH * DIN * LQN];              // values^T split [B,1024,2048]
__device__ bf16  g_vTLo[(size_t)BATCH * DIN * LQN];
__device__ bf16  g_aHi[(size_t)BATCH * DVN * LQN];               // attn split [B,512,2048]
__device__ bf16  g_aLo[(size_t)BATCH * DVN * LQN];
__device__ bf16  g_THi[(size_t)BATCH * DVN * DIN];               // (attn@values) split [B,512,1024]
__device__ bf16  g_TLo[(size_t)BATCH * DVN * DIN];
__device__ bf16  g_WvTHi[DIN * DIN];                             // Wv^T split
__device__ bf16  g_WvTLo[DIN * DIN];

// ---------------------------------------------------------------------------
// Helpers
// ---------------------------------------------------------------------------
__device__ __forceinline__ uint32_t smem_u32(const void* p) {
    uint32_t a;
    asm("{ .reg .u64 t; cvta.to.shared.u64 t, %1; cvt.u32.u64 %0, t; }" : "=r"(a) : "l"(p));
    return a;
}
#define SW128(o) ((o) ^ (((o) >> 3) & 0x70))

__device__ __forceinline__ void cp16(uint32_t dst, const void* src) {
    asm volatile("cp.async.cg.shared.global [%0], [%1], 16;" :: "r"(dst), "l"(src) : "memory");
}
#define CP_COMMIT() asm volatile("cp.async.commit_group;" ::: "memory")
#define CP_WAIT0()  asm volatile("cp.async.wait_group 0;" ::: "memory")

__device__ __forceinline__ void ldsm4(uint32_t& r0, uint32_t& r1, uint32_t& r2, uint32_t& r3, uint32_t a) {
    asm volatile("ldmatrix.sync.aligned.m8n8.x4.shared.b16 {%0,%1,%2,%3}, [%4];"
                 : "=r"(r0), "=r"(r1), "=r"(r2), "=r"(r3) : "r"(a));
}
__device__ __forceinline__ void mma16816(float* d, const uint32_t* a, const uint32_t* b) {
    asm volatile("mma.sync.aligned.m16n8k16.row.col.f32.bf16.bf16.f32 "
                 "{%0,%1,%2,%3},{%4,%5,%6,%7},{%8,%9},{%0,%1,%2,%3};"
                 : "+f"(d[0]), "+f"(d[1]), "+f"(d[2]), "+f"(d[3])
                 : "r"(a[0]), "r"(a[1]), "r"(a[2]), "r"(a[3]), "r"(b[0]), "r"(b[1]));
}
__device__ __forceinline__ void split2(float x, bf16& h, bf16& l) {
    h = __float2bfloat16(x);
    l = __float2bfloat16(x - __bfloat162float(h));
}

// ---------------------------------------------------------------------------
// HMMA bf16-split GEMM:  C[b] = A[b] (MxK) @ B[b]^T  (B is [N,K] K-major)
// A,B as hi/lo bf16 pairs; 3-product split (hi*hi + lo*hi + hi*lo), fp32 acc.
// Block tile 128x128, K-chunk 64, double-buffered cp.async, SW128 swizzle.
// OUT_MODE 0: fp32 C.  OUT_MODE 1: bf16 hi/lo split C.
// M,N multiples of 128; K multiple of 64.
// ---------------------------------------------------------------------------
#define STAGE_BYTES 65536        // Ahi,Alo,Bhi,Blo -- 4 x 16KB
#define MM_SMEM_TOTAL (2 * STAGE_BYTES)

template <int OUT_MODE>
__global__ __launch_bounds__(256, 1)
void mma_gemm(const bf16* __restrict__ Ahi, const bf16* __restrict__ Alo,
              const bf16* __restrict__ Bhi, const bf16* __restrict__ Blo,
              float* __restrict__ Cf, bf16* __restrict__ Chi, bf16* __restrict__ Clo,
              int M, int N, int K,
              long long sA, long long sB, long long sC, int ldc)
{
    extern __shared__ char smem[];
    const uint32_t sb = smem_u32(smem);
    const int tid = threadIdx.x;
    const int lane = tid & 31;
    const int wid = tid >> 5;
    const int warpM = wid & 3;            // 4 warps in M (32 rows each)
    const int warpN = wid >> 2;           // 2 warps in N (64 cols each)
    const int bz = blockIdx.z;
    const int bm = blockIdx.y * 128;
    const int bn = blockIdx.x * 128;

    const char* gsrc[4];
    gsrc[0] = (const char*)(Ahi + (long long)bz * sA + (long long)bm * K);
    gsrc[1] = (const char*)(Alo + (long long)bz * sA + (long long)bm * K);
    gsrc[2] = (const char*)(Bhi + (long long)bz * sB + (long long)bn * K);
    gsrc[3] = (const char*)(Blo + (long long)bz * sB + (long long)bn * K);

    // Per-thread copy coordinates: 16 x 16B per thread per chunk.
    const int cr = tid >> 3;              // 0..31 base row
    const int cs = (tid & 7) << 4;        // byte col within 128B row

    float acc[2][8][4];
    #pragma unroll
    for (int mt = 0; mt < 2; mt++)
        #pragma unroll
        for (int nt = 0; nt < 8; nt++)
            #pragma unroll
            for (int j = 0; j < 4; j++) acc[mt][nt][j] = 0.0f;

    const long long Kb = (long long)K * 2;   // row stride in bytes
    const int NC = K >> 6;

    // Prologue: issue chunk 0
    {
        #pragma unroll
        for (int t = 0; t < 4; t++) {
            const char* s = gsrc[t];
            uint32_t d = sb + t * 16384;
            #pragma unroll
            for (int i = 0; i < 4; i++) {
                int r = cr + i * 32;
                cp16(d + SW128(r * 128 + cs), s + (long long)r * Kb + cs);
            }
        }
        CP_COMMIT();
    }

    // ldmatrix lane coordinates
    const int mrowA = (lane & 7) + ((lane >> 3) & 1) * 8;
    const int kcA   = (lane >> 4) * 16;
    const int nrowB = (lane & 7) + ((lane >> 4) << 3);
    const int kcB   = ((lane >> 3) & 1) * 16;

    for (int c = 0; c < NC; c++) {
        CP_WAIT0();
        __syncthreads();

        if (c + 1 < NC) {
            const int k0b = (c + 1) << 7;          // (c+1)*64 halves * 2B
            uint32_t st = sb + ((c + 1) & 1) * STAGE_BYTES;
            #pragma unroll
            for (int t = 0; t < 4; t++) {
                const char* s = gsrc[t] + k0b;
                uint32_t d = st + t * 16384;
                #pragma unroll
                for (int i = 0; i < 4; i++) {
                    int r = cr + i * 32;
                    cp16(d + SW128(r * 128 + cs), s + (long long)r * Kb + cs);
                }
            }
            CP_COMMIT();
        }

        const uint32_t stg = sb + (c & 1) * STAGE_BYTES;
        const uint32_t bA0 = stg;
        const uint32_t bA1 = stg + 16384;
        const uint32_t bB0 = stg + 32768;
        const uint32_t bB1 = stg + 49152;

        #pragma unroll
        for (int ks = 0; ks < 4; ks++) {
            uint32_t ah[2][4], al[2][4];
            #pragma unroll
            for (int mt = 0; mt < 2; mt++) {
                uint32_t off = SW128((warpM * 32 + mt * 16 + mrowA) * 128 + ks * 32 + kcA);
                ldsm4(ah[mt][0], ah[mt][1], ah[mt][2], ah[mt][3], bA0 + off);
                ldsm4(al[mt][0], al[mt][1], al[mt][2], al[mt][3], bA1 + off);
            }
            uint32_t bh[8][2], bl[8][2];
            #pragma unroll
            for (int np = 0; np < 4; np++) {
                uint32_t off = SW128((warpN * 64 + np * 16 + nrowB) * 128 + ks * 32 + kcB);
                ldsm4(bh[2*np][0], bh[2*np][1], bh[2*np+1][0], bh[2*np+1][1], bB0 + off);
                ldsm4(bl[2*np][0], bl[2*np][1], bl[2*np+1][0], bl[2*np+1][1], bB1 + off);
            }
            #pragma unroll
            for (int mt = 0; mt < 2; mt++)
                #pragma unroll
                for (int nt = 0; nt < 8; nt++) {
                    mma16816(acc[mt][nt], ah[mt], bh[nt]);
                    mma16816(acc[mt][nt], al[mt], bh[nt]);
                    mma16816(acc[mt][nt], ah[mt], bl[nt]);
                }
        }
        __syncthreads();
    }

    // Epilogue: direct global stores (sector-friendly: 4-lane groups cover 32B)
    const long long cbase = (long long)bz * sC;
    #pragma unroll
    for (int mt = 0; mt < 2; mt++) {
        const int r0 = bm + warpM * 32 + mt * 16 + (lane >> 2);
        #pragma unroll
        for (int half = 0; half < 2; half++) {
            const int r = r0 + half * 8;
            const long long rowoff = cbase + (long long)r * ldc + bn + warpN * 64 + (lane & 3) * 2;
            #pragma unroll
            for (int nt = 0; nt < 8; nt++) {
                float x0 = acc[mt][nt][half * 2 + 0];
                float x1 = acc[mt][nt][half * 2 + 1];
                long long off = rowoff + nt * 8;
                if (OUT_MODE == 0) {
                    *(float2*)(Cf + off) = make_float2(x0, x1);
                } else {
                    bf16 h0, l0, h1, l1;
                    split2(x0, h0, l0);
                    split2(x1, h1, l1);
                    uint32_t hp = ((uint32_t)__bfloat16_as_ushort(h1) << 16) | __bfloat16_as_ushort(h0);
                    uint32_t lp = ((uint32_t)__bfloat16_as_ushort(l1) << 16) | __bfloat16_as_ushort(l0);
                    *(uint32_t*)(Chi + off) = hp;
                    *(uint32_t*)(Clo + off) = lp;
                }
            }
        }
    }
}

// ---------------------------------------------------------------------------
// fp32 SIMT GEMM for the small K-projection (M=50): C = A(MxK) @ B(KxN)
// ---------------------------------------------------------------------------
__global__ __launch_bounds__(256)
void gemm128(const float* __restrict__ A, const float* __restrict__ Bm,
             float* __restrict__ C, int M, int N, int K,
             long long sA, long long sB, long long sC, int lda, int ldb, int ldc)
{
    const int b = blockIdx.z;
    A += (long long)b * sA; Bm += (long long)b * sB; C += (long long)b * sC;
    const int bm = blockIdx.y * 128, bn = blockIdx.x * 128;
    __shared__ float As[16][128], Bs[16][128];
    const int tid = threadIdx.x, tx = tid & 15, ty = tid >> 4;
    float acc[8][8];
    #pragma unroll
    for (int i = 0; i < 8; i++)
        #pragma unroll
        for (int j = 0; j < 8; j++) acc[i][j] = 0.0f;

    for (int k0 = 0; k0 < K; k0 += 16) {
        #pragma unroll
        for (int l = 0; l < 2; l++) {
            int t = tid + l * 256, row = t >> 2, col = (t & 3) << 2;
            float4 v = make_float4(0.f, 0.f, 0.f, 0.f);
            if (bm + row < M) v = *(const float4*)(A + (long long)(bm + row) * lda + k0 + col);
            As[col + 0][row] = v.x; As[col + 1][row] = v.y;
            As[col + 2][row] = v.z; As[col + 3][row] = v.w;
        }
        #pragma unroll
        for (int l = 0; l < 2; l++) {
            int t = tid + l * 256, row = t >> 5, col = (t & 31) << 2;
            *(float4*)&Bs[row][col] = *(const float4*)(Bm + (long long)(k0 + row) * ldb + bn + col);
        }
        __syncthreads();
        #pragma unroll
        for (int kk = 0; kk < 16; kk++) {
            float a[8], bb[8];
            float4 a0 = *(const float4*)&As[kk][ty * 8];
            float4 a1 = *(const float4*)&As[kk][ty * 8 + 4];
            a[0]=a0.x; a[1]=a0.y; a[2]=a0.z; a[3]=a0.w; a[4]=a1.x; a[5]=a1.y; a[6]=a1.z; a[7]=a1.w;
            float4 b0 = *(const float4*)&Bs[kk][tx * 8];
            float4 b1 = *(const float4*)&Bs[kk][tx * 8 + 4];
            bb[0]=b0.x; bb[1]=b0.y; bb[2]=b0.z; bb[3]=b0.w; bb[4]=b1.x; bb[5]=b1.y; bb[6]=b1.z; bb[7]=b1.w;
            #pragma unroll
            for (int i = 0; i < 8; i++)
                #pragma unroll
                for (int j = 0; j < 8; j++) acc[i][j] = fmaf(a[i], bb[j], acc[i][j]);
        }
        __syncthreads();
    }
    #pragma unroll
    for (int i = 0; i < 8; i++) {
        int m = bm + ty * 8 + i;
        if (m >= M) continue;
        #pragma unroll
        for (int j = 0; j < 8; j++) C[(long long)m * ldc + bn + tx * 8 + j] = acc[i][j];
    }
}

// ---------------------------------------------------------------------------
// Ut[b,v,h] = (1/32) * sum_k (keys@Wk)[b,k,h] * Wo[k,v], emitted as bf16 hi/lo
// ---------------------------------------------------------------------------
__global__ __launch_bounds__(256)
void u_kernel(const float* __restrict__ kmat, const float* __restrict__ Wo,
              bf16* __restrict__ uhi, bf16* __restrict__ ulo)
{
    const int b = blockIdx.z, h0 = blockIdx.y * 32, v0 = blockIdx.x * 32;
    __shared__ float ks[LKN][32], wo[LKN][32];
    const int tid = threadIdx.x;
    for (int i = tid; i < LKN * 32; i += 256) {
        int kk = i >> 5, c = i & 31;
        ks[kk][c] = kmat[((long long)b * LKN + kk) * DIN + h0 + c];
        wo[kk][c] = Wo[kk * DVN + v0 + c];
    }
    __syncthreads();
    const int hh = tid & 31;
    const int v1 = (tid >> 5) * 4;
    float acc[4] = {0.f, 0.f, 0.f, 0.f};
    for (int kk = 0; kk < LKN; kk++) {
        float kv = ks[kk][hh];
        #pragma unroll
        for (int j = 0; j < 4; j++) acc[j] = fmaf(kv, wo[kk][v1 + j], acc[j]);
    }
    #pragma unroll
    for (int j = 0; j < 4; j++) {
        float x = acc[j] * 0.03125f;
        long long o = ((long long)b * DVN + v0 + v1 + j) * DIN + h0 + hh;
        bf16 h, l; split2(x, h, l);
        uhi[o] = h; ulo[o] = l;
    }
}

// ---------------------------------------------------------------------------
// Elementwise fp32 -> bf16 hi/lo split (n multiple of 1024)
// ---------------------------------------------------------------------------
__global__ __launch_bounds__(256)
void split_plain(const float* __restrict__ in, bf16* __restrict__ hi, bf16* __restrict__ lo)
{
    long long i = ((long long)blockIdx.x * 256 + threadIdx.x) * 4;
    float4 v = *(const float4*)(in + i);
    union { bf16 h[4]; uint2 u; } H, L;
    split2(v.x, H.h[0], L.h[0]); split2(v.y, H.h[1], L.h[1]);
    split2(v.z, H.h[2], L.h[2]); split2(v.w, H.h[3], L.h[3]);
    *(uint2*)(hi + i) = H.u;
    *(uint2*)(lo + i) = L.u;
}

// ---------------------------------------------------------------------------
// Tiled transpose + split: in [R,C] fp32 -> out [C,R] bf16 hi/lo (per batch)
// ---------------------------------------------------------------------------
__global__ __launch_bounds__(256)
void split_trans(const float* __restrict__ in, bf16* __restrict__ hi, bf16* __restrict__ lo,
                 int R, int C)
{
    const int b = blockIdx.z;
    const long long n = (long long)R * C;
    in += b * n; hi += b * n; lo += b * n;
    const int r0 = blockIdx.y * 32, c0 = blockIdx.x * 32;
    __shared__ float t[32][33];
    const int lane = threadIdx.x & 31, wr = threadIdx.x >> 5;
    #pragma unroll
    for (int i = 0; i < 4; i++) {
        int row = wr + i * 8;
        t[row][lane] = in[(long long)(r0 + row) * C + c0 + lane];
    }
    __syncthreads();
    #pragma unroll
    for (int i = 0; i < 4; i++) {
        int row = wr + i * 8;
        float x = t[lane][row];
        long long o = (long long)(c0 + row) * R + r0 + lane;
        bf16 h, l; split2(x, h, l);
        hi[o] = h; lo[o] = l;
    }
}

// ---------------------------------------------------------------------------
// Masked softmax over q for each (b,v) row; also emits bf16 hi/lo of attn.
// ---------------------------------------------------------------------------
__global__ __launch_bounds__(256)
void softmax_mask(float* __restrict__ attn, const int* __restrict__ valid,
                  bf16* __restrict__ ahi, bf16* __restrict__ alo)
{
    const long long row = blockIdx.x;
    const int b = (int)(row / DVN);
    const int vl = valid[b];
    float* p = attn + row * (long long)LQN;
    const int tid = threadIdx.x;
    float v[8];
    float mx = -3.4e38f;
    #pragma unroll
    for (int i = 0; i < 8; i++) {
        int q = tid + i * 256;
        float x = p[q];
        x = (q < vl) ? x : -1000000.0f;
        v[i] = x;
        mx = fmaxf(mx, x);
    }
    __shared__ float red[256];
    red[tid] = mx; __syncthreads();
    for (int s = 128; s > 0; s >>= 1) { if (tid < s) red[tid] = fmaxf(red[tid], red[tid + s]); __syncthreads(); }
    mx = red[0]; __syncthreads();
    float sum = 0.0f;
    #pragma unroll
    for (int i = 0; i < 8; i++) { v[i] = expf(v[i] - mx); sum += v[i]; }
    red[tid] = sum; __syncthreads();
    for (int s = 128; s > 0; s >>= 1) { if (tid < s) red[tid] += red[tid + s]; __syncthreads(); }
    const float inv = 1.0f / red[0];
    #pragma unroll
    for (int i = 0; i < 8; i++) {
        int q = tid + i * 256;
        float y = v[i] * inv;
        p[q] = y;
        bf16 h, l; split2(y, h, l);
        ahi[row * LQN + q] = h;
        alo[row * LQN + q] = l;
    }
}

// ---------------------------------------------------------------------------
extern "C" void kernel_launch(void* const* d_in, const int* in_sizes, int n_in,
                              void* d_out, int out_size)
{
    const float* queries = (const float*)d_in[0];
    const float* keys    = (const float*)d_in[1];
    const float* values  = (const float*)d_in[2];
    const int*   valid   = (const int*)  d_in[3];
    const float* Wq      = (const float*)d_in[4];
    const float* Wk      = (const float*)d_in[5];
    const float* Wv      = (const float*)d_in[6];
    const float* Wo      = (const float*)d_in[7];

    float* out  = (float*)d_out;                         // [32,512,1024]
    float* attn = out + (size_t)BATCH * DVN * DIN;       // [32,512,2048]

    float *pk;
    bf16 *pUtH, *pUtL, *pWqH, *pWqL, *pGtH, *pGtL, *pqH, *pqL;
    bf16 *pvTH, *pvTL, *paH, *paL, *pTH, *pTL, *pWvTH, *pWvTL;
    cudaGetSymbolAddress((void**)&pk,   g_k);
    cudaGetSymbolAddress((void**)&pUtH, g_UtHi); cudaGetSymbolAddress((void**)&pUtL, g_UtLo);
    cudaGetSymbolAddress((void**)&pWqH, g_WqHi); cudaGetSymbolAddress((void**)&pWqL, g_WqLo);
    cudaGetSymbolAddress((void**)&pGtH, g_GtHi); cudaGetSymbolAddress((void**)&pGtL, g_GtLo);
    cudaGetSymbolAddress((void**)&pqH,  g_qHi);  cudaGetSymbolAddress((void**)&pqL,  g_qLo);
    cudaGetSymbolAddress((void**)&pvTH, g_vTHi); cudaGetSymbolAddress((void**)&pvTL, g_vTLo);
    cudaGetSymbolAddress((void**)&paH,  g_aHi);  cudaGetSymbolAddress((void**)&paL,  g_aLo);
    cudaGetSymbolAddress((void**)&pTH,  g_THi);  cudaGetSymbolAddress((void**)&pTL,  g_TLo);
    cudaGetSymbolAddress((void**)&pWvTH, g_WvTHi); cudaGetSymbolAddress((void**)&pWvTL, g_WvTLo);

    cudaFuncSetAttribute(mma_gemm<0>, cudaFuncAttributeMaxDynamicSharedMemorySize, MM_SMEM_TOTAL);
    cudaFuncSetAttribute(mma_gemm<1>, cudaFuncAttributeMaxDynamicSharedMemorySize, MM_SMEM_TOTAL);

    // K1: k = keys @ W_k (fp32 SIMT, small M=50)
    gemm128<<<dim3(DIN / 128, 1, BATCH), 256>>>(
        keys, Wk, pk, LKN, DIN, DIN,
        (long long)LKN * DIN, 0, (long long)LKN * DIN, DIN, DIN, DIN);

    // K2: Ut = (k^T @ W_o / 32)^T  -> bf16 hi/lo [B,512,1024]
    u_kernel<<<dim3(DVN / 32, DIN / 32, BATCH), 256>>>(pk, Wo, pUtH, pUtL);

    // Split Wq
    split_plain<<<(DIN * DIN) / 1024, 256>>>(Wq, pWqH, pWqL);

    // K3: Gt[v,i] = Ut[v,:] . Wq[i,:]   (M=512, N=1024, K=1024) -> bf16 split
    mma_gemm<1><<<dim3(DIN / 128, DVN / 128, BATCH), 256, MM_SMEM_TOTAL>>>(
        pUtH, pUtL, pWqH, pWqL, nullptr, pGtH, pGtL,
        DVN, DIN, DIN, (long long)DVN * DIN, 0, (long long)DVN * DIN, DIN);

    // Split queries
    split_plain<<<(int)(((long long)BATCH * LQN * DIN) / 1024), 256>>>(queries, pqH, pqL);

    // K4: scores[v,q] = Gt[v,:] . queries[q,:]  (M=512, N=2048, K=1024) -> fp32 attn buf
    mma_gemm<0><<<dim3(LQN / 128, DVN / 128, BATCH), 256, MM_SMEM_TOTAL>>>(
        pGtH, pGtL, pqH, pqL, attn, nullptr, nullptr,
        DVN, LQN, DIN, (long long)DVN * DIN, (long long)LQN * DIN, (long long)DVN * LQN, LQN);

    // K5: masked softmax over q (also emit bf16 split of attn)
    softmax_mask<<<BATCH * DVN, 256>>>(attn, valid, paH, paL);

    // Transpose+split values -> vT [B,1024,2048]
    split_trans<<<dim3(DIN / 32, LQN / 32, BATCH), 256>>>(values, pvTH, pvTL, LQN, DIN);

    // K6: T[v,d] = attn[v,:] . vT[d,:]  (M=512, N=1024, K=2048) -> bf16 split
    mma_gemm<1><<<dim3(DIN / 128, DVN / 128, BATCH), 256, MM_SMEM_TOTAL>>>(
        paH, paL, pvTH, pvTL, nullptr, pTH, pTL,
        DVN, DIN, LQN, (long long)DVN * LQN, (long long)DIN * LQN, (long long)DVN * DIN, DIN);

    // Transpose+split Wv -> WvT [1024,1024]
    split_trans<<<dim3(DIN / 32, DIN / 32, 1), 256>>>(Wv, pWvTH, pWvTL, DIN, DIN);

    // K7: out[v,h] = T[v,:] . WvT[h,:]  (M=512, N=1024, K=1024) -> fp32 out
    mma_gemm<0><<<dim3(DIN / 128, DVN / 128, BATCH), 256, MM_SMEM_TOTAL>>>(
        pTH, pTL, pWvTH, pWvTL, out, nullptr, nullptr,
        DVN, DIN, DIN, (long long)DVN * DIN, 0, (long long)DVN * DIN, DIN);
}